// round 14
// baseline (speedup 1.0000x reference)
#include <cuda_runtime.h>
#include <cuda_fp16.h>

// Problem constants (fixed by setup_inputs): N=50000, E=800000, F=64, U=64, H=8
#define Fd   64
#define Hh   8
#define HU   512          // H * U
#define NMAX 50000
#define EMAX 800000
#define CHUNK 64          // edges per warp in k_edge

// ---------------- static scratch (no allocations allowed) ----------------
__device__ __align__(16) __half d_g[(size_t)NMAX * HU];   // g fp16 (~51 MB)
__device__ __align__(16) uint2  d_x16[(size_t)NMAX * 16]; // X in fp16 (4 halves per uint2)
__device__ __align__(16) uint2  d_Cfrag[4 * 64 * 32];     // B fragments, 64 KB (kt, nt, lane)
__device__ float d_asrc[NMAX * Hh];
__device__ float d_adst[NMAX * Hh];
__device__ __align__(16) float d_asum[NMAX * Hh];         // per (src,h) attention sums
__device__ __align__(16) float d_oacc[(size_t)NMAX * Fd]; // pre-leaky output accumulator
__device__ float d_wa[2 * Hh * Fd];                       // folded attention vectors

__device__ __forceinline__ float leaky(float v) { return v >= 0.f ? v : 0.2f * v; }

__device__ __forceinline__ void mma16816(float* c, unsigned a0, unsigned a1,
                                         unsigned a2, unsigned a3,
                                         unsigned b0, unsigned b1) {
    asm volatile(
        "mma.sync.aligned.m16n8k16.row.col.f32.f16.f16.f32 "
        "{%0,%1,%2,%3}, {%4,%5,%6,%7}, {%8,%9}, {%0,%1,%2,%3};\n"
        : "+f"(c[0]), "+f"(c[1]), "+f"(c[2]), "+f"(c[3])
        : "r"(a0), "r"(a1), "r"(a2), "r"(a3), "r"(b0), "r"(b1));
}

// ---------------- K0: fold weights into B-fragments + wa; x->fp16; zero accums -----
__global__ void k_prep(const float* __restrict__ W, const float* __restrict__ a,
                       const float* __restrict__ M, const float* __restrict__ x, int N) {
    int idx = blockIdx.x * blockDim.x + threadIdx.x;
    int nthr = gridDim.x * blockDim.x;

    if (idx < 4 * 64 * 32) {
        int kt = idx >> 11, rem = idx & 2047;
        int nt = rem >> 5, lane = rem & 31;
        int p = lane & 3, q = lane >> 2;
        int n = nt * 8 + q;
        int h = n >> 6, j = n & 63;
        int f0 = kt * 16 + p * 2;
        float c4[4];
#pragma unroll
        for (int k = 0; k < 4; ++k) {
            int f = f0 + (k >> 1) * 8 + (k & 1);
            const float* Wp = W + (h * Fd + f) * 64;
            const float* Mp = M + h * 64 * 64 + j;
            float s = 0.f;
#pragma unroll 8
            for (int u = 0; u < 64; ++u) s += __ldg(Wp + u) * __ldg(Mp + u * 64);
            c4[k] = s;
        }
        __half2 lo = __floats2half2_rn(c4[0], c4[1]);
        __half2 hi = __floats2half2_rn(c4[2], c4[3]);
        uint2 v;
        v.x = *(unsigned*)&lo;
        v.y = *(unsigned*)&hi;
        d_Cfrag[idx] = v;
    }
    if (idx < 2 * Hh * Fd) {                        // 1024 entries
        int which = idx >> 9;
        int r = idx & 511;
        int h = r >> 6, f = r & 63;
        const float* Wp = W + (h * Fd + f) * 64;
        const float* ap = a + h * 128 + which * 64;
        float s = 0.f;
#pragma unroll 8
        for (int u = 0; u < 64; ++u) s += __ldg(Wp + u) * __ldg(ap + u);
        d_wa[idx] = s;
    }

    // x -> fp16 (grid-strided)
    int total4 = N * 16;
    for (int i = idx; i < total4; i += nthr) {
        float4 v = __ldg((const float4*)x + i);
        __half2 lo = __floats2half2_rn(v.x, v.y);
        __half2 hi = __floats2half2_rn(v.z, v.w);
        uint2 u;
        u.x = *(unsigned*)&lo;
        u.y = *(unsigned*)&hi;
        d_x16[i] = u;
    }

    // zero accumulators
    float4 z = make_float4(0.f, 0.f, 0.f, 0.f);
    int n_oacc4 = N * Fd / 4;
    for (int i = idx; i < n_oacc4; i += nthr) ((float4*)d_oacc)[i] = z;
    int n_asum4 = N * Hh / 4;
    for (int i = idx; i < n_asum4; i += nthr) ((float4*)d_asum)[i] = z;
}

// ---------------- K1: alpha_src/alpha_dst, smem-tiled (conflict-free) --------------
__global__ void __launch_bounds__(256) k_alpha(const float* __restrict__ x, int N) {
    __shared__ float sx[16][65];
    __shared__ float swa[16][65];
    int tid = threadIdx.x;
    int n0 = blockIdx.x * 16;

    for (int i = tid; i < 1024; i += 256) swa[i >> 6][i & 63] = d_wa[i];
    for (int i = tid; i < 1024; i += 256) {
        int row = i >> 6, col = i & 63;
        sx[row][col] = (n0 + row < N) ? __ldg(x + (size_t)(n0 + row) * 64 + col) : 0.f;
    }
    __syncthreads();

    int ln = tid >> 4;          // local node 0..15
    int r  = tid & 15;          // which*8 + h
    float s = 0.f;
#pragma unroll
    for (int u = 0; u < 64; ++u) s += sx[ln][u] * swa[r][u];

    int n = n0 + ln;
    if (n < N) {
        int which = r >> 3, h = r & 7;
        if (which) d_adst[n * 8 + h] = s;
        else       d_asrc[n * 8 + h] = s;
    }
}

// ---------------- K2: attention segment sums (8 edges/warp, loads front-loaded) ----
__global__ void k_att(const int* __restrict__ edges, int E) {
    int gw = (blockIdx.x * blockDim.x + threadIdx.x) >> 5;
    int lane = threadIdx.x & 31;
    int i = lane >> 3, h = lane & 7;
    int base = gw * 8;
    int e0 = base + i, e1 = base + 4 + i;
    bool v0 = e0 < E, v1 = e1 < E;

    int2 ed0 = make_int2(-1 - i, 0), ed1 = make_int2(-9 - i, 0);
    if (v0) ed0 = __ldg((const int2*)edges + e0);
    if (v1) ed1 = __ldg((const int2*)edges + e1);
    float as0 = v0 ? __ldg(d_asrc + ed0.x * 8 + h) : 0.f;
    float as1 = v1 ? __ldg(d_asrc + ed1.x * 8 + h) : 0.f;
    float ad0 = v0 ? __ldg(d_adst + ed0.y * 8 + h) : 0.f;
    float ad1 = v1 ? __ldg(d_adst + ed1.y * 8 + h) : 0.f;

    float att0 = 0.f, att1 = 0.f;
    if (v0) {
        float s = as0 + ad0;
        s = s >= 0.f ? s : 0.2f * s;
        s = fminf(2.f, fmaxf(-2.f, s));
        att0 = __expf(s);
    }
    if (v1) {
        float s = as1 + ad1;
        s = s >= 0.f ? s : 0.2f * s;
        s = fminf(2.f, fmaxf(-2.f, s));
        att1 = __expf(s);
    }

    unsigned full = 0xffffffffu;
    {
        int   s1 = __shfl_down_sync(full, ed0.x, 8);
        float q1 = __shfl_down_sync(full, att0, 8);
        float w1 = att0 + ((i < 3 && s1 == ed0.x) ? q1 : 0.f);
        int   s2 = __shfl_down_sync(full, ed0.x, 16);
        float q2 = __shfl_down_sync(full, w1, 16);
        float w2 = w1 + ((i < 2 && s2 == ed0.x) ? q2 : 0.f);
        int sp = __shfl_up_sync(full, ed0.x, 8);
        bool head = (i == 0) || (sp != ed0.x);
        if (v0 && head) atomicAdd(&d_asum[ed0.x * 8 + h], w2);
    }
    {
        int   s1 = __shfl_down_sync(full, ed1.x, 8);
        float q1 = __shfl_down_sync(full, att1, 8);
        float w1 = att1 + ((i < 3 && s1 == ed1.x) ? q1 : 0.f);
        int   s2 = __shfl_down_sync(full, ed1.x, 16);
        float q2 = __shfl_down_sync(full, w1, 16);
        float w2 = w1 + ((i < 2 && s2 == ed1.x) ? q2 : 0.f);
        int sp = __shfl_up_sync(full, ed1.x, 8);
        bool head = (i == 0) || (sp != ed1.x);
        if (v1 && head) atomicAdd(&d_asum[ed1.x * 8 + h], w2);
    }
}

// ---------------- K3: g = X @ C tensor cores; small tiles for 4 blocks/SM -----------
// grid = (ceil(N/64), 4). Block = 64 rows x 128 cols. Warp = 16 rows x 64 cols
// (8 n8-tiles, acc = 32 regs -> ~64 total -> 4 blocks/SM = 32 warps).
__global__ void __launch_bounds__(256) k_mma(int N) {
    __shared__ unsigned sx[64][36];     // 9216 B
    __shared__ unsigned so[64][68];     // 17408 B (64 half2 cols + 4 pad)
    int tid = threadIdx.x;
    int warp = tid >> 5, lane = tid & 31;
    int p = lane & 3, q = lane >> 2;
    int rblk = blockIdx.x * 64;

    // stage x (coalesced global reads)
    const unsigned* xu = (const unsigned*)d_x16;   // 32 words per row
    for (int i = tid; i < 2048; i += 256) {
        int row = i >> 5, c = i & 31;
        int gr = min(rblk + row, N - 1);
        sx[row][c] = xu[(size_t)gr * 32 + c];
    }
    __syncthreads();

    int r0 = (warp >> 1) * 16;                     // local row base
    int nt0 = (warp & 1) * 8;                      // local n8-tile base (of 16)
    int ntg = blockIdx.y * 16 + nt0;               // global n8-tile base

    float acc[8][4];
#pragma unroll
    for (int t = 0; t < 8; ++t) {
        acc[t][0] = 0.f; acc[t][1] = 0.f; acc[t][2] = 0.f; acc[t][3] = 0.f;
    }

#pragma unroll
    for (int kt = 0; kt < 4; ++kt) {
        unsigned a0 = sx[r0 + q][kt * 8 + p];
        unsigned a1 = sx[r0 + q + 8][kt * 8 + p];
        unsigned a2 = sx[r0 + q][kt * 8 + p + 4];
        unsigned a3 = sx[r0 + q + 8][kt * 8 + p + 4];
        const uint2* bf = d_Cfrag + (kt * 64 + ntg) * 32 + lane;
#pragma unroll
        for (int nt = 0; nt < 8; ++nt) {
            uint2 b = __ldg(bf + nt * 32);
            mma16816(acc[nt], a0, a1, a2, a3, b.x, b.y);
        }
    }

    // stage output fragments to smem (conflict-free: bank = 4q+p+const)
#pragma unroll
    for (int nt = 0; nt < 8; ++nt) {
        int c = (nt0 + nt) * 4 + p;                // half2 col within 64
        __half2 h01 = __floats2half2_rn(acc[nt][0], acc[nt][1]);
        __half2 h23 = __floats2half2_rn(acc[nt][2], acc[nt][3]);
        so[r0 + q][c] = *(unsigned*)&h01;
        so[r0 + q + 8][c] = *(unsigned*)&h23;
    }
    __syncthreads();

    // coalesced STG.128 of the 64 x 128-col tile
    uint4* g4 = (uint4*)d_g;                       // 64 uint4 per row
    for (int i = tid; i < 1024; i += 256) {
        int row = i >> 4, c4 = i & 15;
        int gr = rblk + row;
        if (gr < N) {
            uint4 v = *(const uint4*)&so[row][c4 * 4];
            g4[(size_t)gr * 64 + blockIdx.y * 16 + c4] = v;
        }
    }
}

// ---------------- K4: edge aggregation helpers ----------------
__device__ __forceinline__ void flush_acc(float* acc, int cur, int lane) {
    unsigned full = 0xffffffffu;
#pragma unroll
    for (int k = 0; k < 8; ++k) acc[k] += __shfl_down_sync(full, acc[k], 8);
#pragma unroll
    for (int k = 0; k < 8; ++k) acc[k] += __shfl_down_sync(full, acc[k], 16);
    if (lane < 8) {
#pragma unroll
        for (int k = 0; k < 8; ++k)
            atomicAdd(&d_oacc[(size_t)cur * 64 + lane * 8 + k], acc[k]);
    }
#pragma unroll
    for (int k = 0; k < 8; ++k) acc[k] = 0.f;
}

__device__ __forceinline__ void do_edge(int2 ed, float ad, uint4 g0, uint4 g1,
                                        float* acc, int& cur, float& rs, float& asrcv,
                                        int lane, int hA) {
    unsigned full = 0xffffffffu;
    if (ed.x != cur) {                             // warp-uniform
        if (cur >= 0) flush_acc(acc, cur, lane);
        cur = ed.x;
        if (lane < 8) {
            asrcv = __ldg(d_asrc + cur * 8 + lane);
            rs = 1.f / __ldg(d_asum + cur * 8 + lane);
        }
    }
    float wl = 0.f;
    if (lane < 8) {
        float s = asrcv + ad;
        s = s >= 0.f ? s : 0.2f * s;
        s = fminf(2.f, fmaxf(-2.f, s));
        wl = __expf(s) * rs;
    }
    float w0 = __shfl_sync(full, wl, hA);
    float w1 = __shfl_sync(full, wl, hA + 4);
    float2 f;
    f = __half22float2(*(__half2*)&g0.x); acc[0] += w0 * f.x; acc[1] += w0 * f.y;
    f = __half22float2(*(__half2*)&g0.y); acc[2] += w0 * f.x; acc[3] += w0 * f.y;
    f = __half22float2(*(__half2*)&g0.z); acc[4] += w0 * f.x; acc[5] += w0 * f.y;
    f = __half22float2(*(__half2*)&g0.w); acc[6] += w0 * f.x; acc[7] += w0 * f.y;
    f = __half22float2(*(__half2*)&g1.x); acc[0] += w1 * f.x; acc[1] += w1 * f.y;
    f = __half22float2(*(__half2*)&g1.y); acc[2] += w1 * f.x; acc[3] += w1 * f.y;
    f = __half22float2(*(__half2*)&g1.z); acc[4] += w1 * f.x; acc[5] += w1 * f.y;
    f = __half22float2(*(__half2*)&g1.w); acc[6] += w1 * f.x; acc[7] += w1 * f.y;
}

// ---------------- K4: edge aggregation, 4-edge load batching (8 LDG.128 in flight) --
// Lane layout: load i (0/1) gives lane cols (i*32+lane)*8: head = i*4 + (lane>>3),
// j-block = (lane&7)*8. Lane sums its 8 j-values over its 2 heads; full head
// reduction (down 8, down 16) at flush.
__global__ void k_edge(const int* __restrict__ edges, int E) {
    int gw = (blockIdx.x * blockDim.x + threadIdx.x) >> 5;
    int lane = threadIdx.x & 31;
    int e0 = gw * CHUNK;
    if (e0 >= E) return;
    int e1 = min(e0 + CHUNK, E);

    const uint4* __restrict__ gb = (const uint4*)d_g;     // 64 uint4 per row
    float acc[8] = {0.f, 0.f, 0.f, 0.f, 0.f, 0.f, 0.f, 0.f};
    float rs = 0.f, asrcv = 0.f;
    int cur = -1;
    int hA = lane >> 3;

    for (int e = e0; e < e1; e += 4) {
        int2 ed[4];
#pragma unroll
        for (int t = 0; t < 4; ++t)
            ed[t] = __ldg((const int2*)edges + min(e + t, E - 1));
        float ad[4];
#pragma unroll
        for (int t = 0; t < 4; ++t)
            ad[t] = (lane < 8) ? __ldg(d_adst + ed[t].y * 8 + lane) : 0.f;
        uint4 ga[4], gc[4];
#pragma unroll
        for (int t = 0; t < 4; ++t) {
            ga[t] = __ldg(gb + (size_t)ed[t].y * 64 + lane);
            gc[t] = __ldg(gb + (size_t)ed[t].y * 64 + 32 + lane);
        }
#pragma unroll
        for (int t = 0; t < 4; ++t)
            if (e + t < e1)                         // warp-uniform
                do_edge(ed[t], ad[t], ga[t], gc[t], acc, cur, rs, asrcv, lane, hA);
    }
    if (cur >= 0) flush_acc(acc, cur, lane);
}

// ---------------- K5: final leaky ----------------
__global__ void k_final(float* __restrict__ out, int total) {
    int i = blockIdx.x * blockDim.x + threadIdx.x;
    if (i < total) out[i] = leaky(d_oacc[i]);
}

// ---------------- launch ----------------
extern "C" void kernel_launch(void* const* d_in, const int* in_sizes, int n_in,
                              void* d_out, int out_size) {
    const float* x     = (const float*)d_in[0];
    const int*   edges = (const int*)  d_in[1];
    const float* W     = (const float*)d_in[2];
    const float* a     = (const float*)d_in[3];
    const float* M     = (const float*)d_in[4];
    float* out = (float*)d_out;

    int N = in_sizes[0] / Fd;
    int E = in_sizes[1] / 2;

    k_prep<<<256, 256>>>(W, a, M, x, N);                               // #1
    k_alpha<<<(N + 15) / 16, 256>>>(x, N);                             // #2
    k_att<<<((E + 7) / 8 * 32 + 255) / 256, 256>>>(edges, E);          // #3
    dim3 mg((N + 63) / 64, 4);
    k_mma<<<mg, 256>>>(N);                                             // #4
    int nwarps = (E + CHUNK - 1) / CHUNK;
    k_edge<<<(nwarps * 32 + 255) / 256, 256>>>(edges, E);              // #5
    k_final<<<(N * Fd + 255) / 256, 256>>>(out, N * Fd);               // #6
}

// round 15
// speedup vs baseline: 1.0407x; 1.0407x over previous
#include <cuda_runtime.h>
#include <cuda_fp16.h>

// Problem constants (fixed by setup_inputs): N=50000, E=800000, F=64, U=64, H=8
#define Fd   64
#define Hh   8
#define HU   512          // H * U
#define NMAX 50000
#define EMAX 800000
#define CHUNK 64          // edges per warp in k_edge

// ---------------- static scratch (no allocations allowed) ----------------
__device__ __align__(16) __half d_g[(size_t)NMAX * HU];   // g fp16 (~51 MB)
__device__ __align__(16) uint2  d_x16[(size_t)NMAX * 16]; // X in fp16 (4 halves per uint2)
__device__ __align__(16) uint2  d_Cfrag[4 * 64 * 32];     // B fragments, 64 KB (kt, nt, lane)
__device__ float d_asrc[NMAX * Hh];
__device__ float d_adst[NMAX * Hh];
__device__ __align__(16) float d_asum[NMAX * Hh];         // per (src,h) attention sums
__device__ __align__(16) float d_oacc[(size_t)NMAX * Fd]; // pre-leaky output accumulator
__device__ float d_wa[2 * Hh * Fd];                       // folded attention vectors

__device__ __forceinline__ float leaky(float v) { return v >= 0.f ? v : 0.2f * v; }

__device__ __forceinline__ void mma16816(float* c, unsigned a0, unsigned a1,
                                         unsigned a2, unsigned a3,
                                         unsigned b0, unsigned b1) {
    asm volatile(
        "mma.sync.aligned.m16n8k16.row.col.f32.f16.f16.f32 "
        "{%0,%1,%2,%3}, {%4,%5,%6,%7}, {%8,%9}, {%0,%1,%2,%3};\n"
        : "+f"(c[0]), "+f"(c[1]), "+f"(c[2]), "+f"(c[3])
        : "r"(a0), "r"(a1), "r"(a2), "r"(a3), "r"(b0), "r"(b1));
}

// ---------------- K0: fold weights into B-fragments + wa; x->fp16; zero accums -----
__global__ void k_prep(const float* __restrict__ W, const float* __restrict__ a,
                       const float* __restrict__ M, const float* __restrict__ x, int N) {
    int idx = blockIdx.x * blockDim.x + threadIdx.x;
    int nthr = gridDim.x * blockDim.x;

    if (idx < 4 * 64 * 32) {
        int kt = idx >> 11, rem = idx & 2047;
        int nt = rem >> 5, lane = rem & 31;
        int p = lane & 3, q = lane >> 2;
        int n = nt * 8 + q;
        int h = n >> 6, j = n & 63;
        int f0 = kt * 16 + p * 2;
        float c4[4];
#pragma unroll
        for (int k = 0; k < 4; ++k) {
            int f = f0 + (k >> 1) * 8 + (k & 1);
            const float* Wp = W + (h * Fd + f) * 64;
            const float* Mp = M + h * 64 * 64 + j;
            float s = 0.f;
#pragma unroll 8
            for (int u = 0; u < 64; ++u) s += __ldg(Wp + u) * __ldg(Mp + u * 64);
            c4[k] = s;
        }
        __half2 lo = __floats2half2_rn(c4[0], c4[1]);
        __half2 hi = __floats2half2_rn(c4[2], c4[3]);
        uint2 v;
        v.x = *(unsigned*)&lo;
        v.y = *(unsigned*)&hi;
        d_Cfrag[idx] = v;
    }
    if (idx < 2 * Hh * Fd) {                        // 1024 entries
        int which = idx >> 9;
        int r = idx & 511;
        int h = r >> 6, f = r & 63;
        const float* Wp = W + (h * Fd + f) * 64;
        const float* ap = a + h * 128 + which * 64;
        float s = 0.f;
#pragma unroll 8
        for (int u = 0; u < 64; ++u) s += __ldg(Wp + u) * __ldg(ap + u);
        d_wa[idx] = s;
    }

    // x -> fp16 (grid-strided)
    int total4 = N * 16;
    for (int i = idx; i < total4; i += nthr) {
        float4 v = __ldg((const float4*)x + i);
        __half2 lo = __floats2half2_rn(v.x, v.y);
        __half2 hi = __floats2half2_rn(v.z, v.w);
        uint2 u;
        u.x = *(unsigned*)&lo;
        u.y = *(unsigned*)&hi;
        d_x16[i] = u;
    }

    // zero accumulators
    float4 z = make_float4(0.f, 0.f, 0.f, 0.f);
    int n_oacc4 = N * Fd / 4;
    for (int i = idx; i < n_oacc4; i += nthr) ((float4*)d_oacc)[i] = z;
    int n_asum4 = N * Hh / 4;
    for (int i = idx; i < n_asum4; i += nthr) ((float4*)d_asum)[i] = z;
}

// ---------------- K1: alpha_src/alpha_dst, smem-tiled (conflict-free) --------------
__global__ void __launch_bounds__(256) k_alpha(const float* __restrict__ x, int N) {
    __shared__ float sx[16][65];
    __shared__ float swa[16][65];
    int tid = threadIdx.x;
    int n0 = blockIdx.x * 16;

    for (int i = tid; i < 1024; i += 256) swa[i >> 6][i & 63] = d_wa[i];
    for (int i = tid; i < 1024; i += 256) {
        int row = i >> 6, col = i & 63;
        sx[row][col] = (n0 + row < N) ? __ldg(x + (size_t)(n0 + row) * 64 + col) : 0.f;
    }
    __syncthreads();

    int ln = tid >> 4;          // local node 0..15
    int r  = tid & 15;          // which*8 + h
    float s = 0.f;
#pragma unroll
    for (int u = 0; u < 64; ++u) s += sx[ln][u] * swa[r][u];

    int n = n0 + ln;
    if (n < N) {
        int which = r >> 3, h = r & 7;
        if (which) d_adst[n * 8 + h] = s;
        else       d_asrc[n * 8 + h] = s;
    }
}

// ---------------- K2: attention segment sums (8 edges/warp, loads front-loaded) ----
__global__ void k_att(const int* __restrict__ edges, int E) {
    int gw = (blockIdx.x * blockDim.x + threadIdx.x) >> 5;
    int lane = threadIdx.x & 31;
    int i = lane >> 3, h = lane & 7;
    int base = gw * 8;
    int e0 = base + i, e1 = base + 4 + i;
    bool v0 = e0 < E, v1 = e1 < E;

    int2 ed0 = make_int2(-1 - i, 0), ed1 = make_int2(-9 - i, 0);
    if (v0) ed0 = __ldg((const int2*)edges + e0);
    if (v1) ed1 = __ldg((const int2*)edges + e1);
    float as0 = v0 ? __ldg(d_asrc + ed0.x * 8 + h) : 0.f;
    float as1 = v1 ? __ldg(d_asrc + ed1.x * 8 + h) : 0.f;
    float ad0 = v0 ? __ldg(d_adst + ed0.y * 8 + h) : 0.f;
    float ad1 = v1 ? __ldg(d_adst + ed1.y * 8 + h) : 0.f;

    float att0 = 0.f, att1 = 0.f;
    if (v0) {
        float s = as0 + ad0;
        s = s >= 0.f ? s : 0.2f * s;
        s = fminf(2.f, fmaxf(-2.f, s));
        att0 = __expf(s);
    }
    if (v1) {
        float s = as1 + ad1;
        s = s >= 0.f ? s : 0.2f * s;
        s = fminf(2.f, fmaxf(-2.f, s));
        att1 = __expf(s);
    }

    unsigned full = 0xffffffffu;
    {
        int   s1 = __shfl_down_sync(full, ed0.x, 8);
        float q1 = __shfl_down_sync(full, att0, 8);
        float w1 = att0 + ((i < 3 && s1 == ed0.x) ? q1 : 0.f);
        int   s2 = __shfl_down_sync(full, ed0.x, 16);
        float q2 = __shfl_down_sync(full, w1, 16);
        float w2 = w1 + ((i < 2 && s2 == ed0.x) ? q2 : 0.f);
        int sp = __shfl_up_sync(full, ed0.x, 8);
        bool head = (i == 0) || (sp != ed0.x);
        if (v0 && head) atomicAdd(&d_asum[ed0.x * 8 + h], w2);
    }
    {
        int   s1 = __shfl_down_sync(full, ed1.x, 8);
        float q1 = __shfl_down_sync(full, att1, 8);
        float w1 = att1 + ((i < 3 && s1 == ed1.x) ? q1 : 0.f);
        int   s2 = __shfl_down_sync(full, ed1.x, 16);
        float q2 = __shfl_down_sync(full, w1, 16);
        float w2 = w1 + ((i < 2 && s2 == ed1.x) ? q2 : 0.f);
        int sp = __shfl_up_sync(full, ed1.x, 8);
        bool head = (i == 0) || (sp != ed1.x);
        if (v1 && head) atomicAdd(&d_asum[ed1.x * 8 + h], w2);
    }
}

// ---------------- K3: g = X @ C tensor cores; small tiles for 4 blocks/SM -----------
// grid = (ceil(N/64), 4). Block = 64 rows x 128 cols. Warp = 16 rows x 64 cols
// (8 n8-tiles, acc = 32 regs -> 64 total -> 4 blocks/SM = 32 warps). [31.3us measured]
__global__ void __launch_bounds__(256) k_mma(int N) {
    __shared__ unsigned sx[64][36];     // 9216 B
    __shared__ unsigned so[64][68];     // 17408 B (64 half2 cols + 4 pad)
    int tid = threadIdx.x;
    int warp = tid >> 5, lane = tid & 31;
    int p = lane & 3, q = lane >> 2;
    int rblk = blockIdx.x * 64;

    // stage x (coalesced global reads)
    const unsigned* xu = (const unsigned*)d_x16;   // 32 words per row
    for (int i = tid; i < 2048; i += 256) {
        int row = i >> 5, c = i & 31;
        int gr = min(rblk + row, N - 1);
        sx[row][c] = xu[(size_t)gr * 32 + c];
    }
    __syncthreads();

    int r0 = (warp >> 1) * 16;                     // local row base
    int nt0 = (warp & 1) * 8;                      // local n8-tile base (of 16)
    int ntg = blockIdx.y * 16 + nt0;               // global n8-tile base

    float acc[8][4];
#pragma unroll
    for (int t = 0; t < 8; ++t) {
        acc[t][0] = 0.f; acc[t][1] = 0.f; acc[t][2] = 0.f; acc[t][3] = 0.f;
    }

#pragma unroll
    for (int kt = 0; kt < 4; ++kt) {
        unsigned a0 = sx[r0 + q][kt * 8 + p];
        unsigned a1 = sx[r0 + q + 8][kt * 8 + p];
        unsigned a2 = sx[r0 + q][kt * 8 + p + 4];
        unsigned a3 = sx[r0 + q + 8][kt * 8 + p + 4];
        const uint2* bf = d_Cfrag + (kt * 64 + ntg) * 32 + lane;
#pragma unroll
        for (int nt = 0; nt < 8; ++nt) {
            uint2 b = __ldg(bf + nt * 32);
            mma16816(acc[nt], a0, a1, a2, a3, b.x, b.y);
        }
    }

    // stage output fragments to smem (conflict-free: bank = 4q+p+const)
#pragma unroll
    for (int nt = 0; nt < 8; ++nt) {
        int c = (nt0 + nt) * 4 + p;                // half2 col within 64
        __half2 h01 = __floats2half2_rn(acc[nt][0], acc[nt][1]);
        __half2 h23 = __floats2half2_rn(acc[nt][2], acc[nt][3]);
        so[r0 + q][c] = *(unsigned*)&h01;
        so[r0 + q + 8][c] = *(unsigned*)&h23;
    }
    __syncthreads();

    // coalesced STG.128 of the 64 x 128-col tile
    uint4* g4 = (uint4*)d_g;                       // 64 uint4 per row
    for (int i = tid; i < 1024; i += 256) {
        int row = i >> 4, c4 = i & 15;
        int gr = rblk + row;
        if (gr < N) {
            uint4 v = *(const uint4*)&so[row][c4 * 4];
            g4[(size_t)gr * 64 + blockIdx.y * 16 + c4] = v;
        }
    }
}

// ---------------- K4: edge aggregation, uint4 g loads, 2-edge unroll (R12 version) --
// Lane layout: load i (0/1) gives lane cols (i*32+lane)*8: head = i*4 + (lane>>3),
// j-block = (lane&7)*8. Lane sums its 8 j-values over its 2 heads; full head
// reduction (down 8, down 16) at flush.
__global__ void k_edge(const int* __restrict__ edges, int E) {
    int gw = (blockIdx.x * blockDim.x + threadIdx.x) >> 5;
    int lane = threadIdx.x & 31;
    int e0 = gw * CHUNK;
    if (e0 >= E) return;
    int e1 = min(e0 + CHUNK, E);

    const uint4* __restrict__ gb = (const uint4*)d_g;     // 64 uint4 per row
    float acc[8] = {0.f, 0.f, 0.f, 0.f, 0.f, 0.f, 0.f, 0.f};
    float rs = 0.f, asrcv = 0.f;
    int cur = -1;
    unsigned full = 0xffffffffu;
    int hA = lane >> 3;                           // head for load 0; load 1 -> hA+4

    for (int e = e0; e < e1; e += 2) {
        bool hasB = (e + 1 < e1);
        int2 edA = __ldg((const int2*)edges + e);
        int2 edB = hasB ? __ldg((const int2*)edges + (e + 1)) : edA;
        float adA = (lane < 8) ? __ldg(d_adst + edA.y * 8 + lane) : 0.f;
        float adB = (lane < 8) ? __ldg(d_adst + edB.y * 8 + lane) : 0.f;

        uint4 gA0 = __ldg(gb + (size_t)edA.y * 64 + lane);
        uint4 gA1 = __ldg(gb + (size_t)edA.y * 64 + 32 + lane);
        uint4 gB0 = __ldg(gb + (size_t)edB.y * 64 + lane);
        uint4 gB1 = __ldg(gb + (size_t)edB.y * 64 + 32 + lane);

        // ---- edge A ----
        if (edA.x != cur) {                        // warp-uniform
            if (cur >= 0) {
#pragma unroll
                for (int k = 0; k < 8; ++k)
                    acc[k] += __shfl_down_sync(full, acc[k], 8);
#pragma unroll
                for (int k = 0; k < 8; ++k)
                    acc[k] += __shfl_down_sync(full, acc[k], 16);
                if (lane < 8) {
#pragma unroll
                    for (int k = 0; k < 8; ++k)
                        atomicAdd(&d_oacc[(size_t)cur * 64 + lane * 8 + k], acc[k]);
                }
#pragma unroll
                for (int k = 0; k < 8; ++k) acc[k] = 0.f;
            }
            cur = edA.x;
            if (lane < 8) {
                asrcv = __ldg(d_asrc + cur * 8 + lane);
                rs = 1.f / __ldg(d_asum + cur * 8 + lane);
            }
        }
        {
            float wl = 0.f;
            if (lane < 8) {
                float s = asrcv + adA;
                s = s >= 0.f ? s : 0.2f * s;
                s = fminf(2.f, fmaxf(-2.f, s));
                wl = __expf(s) * rs;
            }
            float w0 = __shfl_sync(full, wl, hA);
            float w1 = __shfl_sync(full, wl, hA + 4);
            float2 f;
            f = __half22float2(*(__half2*)&gA0.x); acc[0] += w0 * f.x; acc[1] += w0 * f.y;
            f = __half22float2(*(__half2*)&gA0.y); acc[2] += w0 * f.x; acc[3] += w0 * f.y;
            f = __half22float2(*(__half2*)&gA0.z); acc[4] += w0 * f.x; acc[5] += w0 * f.y;
            f = __half22float2(*(__half2*)&gA0.w); acc[6] += w0 * f.x; acc[7] += w0 * f.y;
            f = __half22float2(*(__half2*)&gA1.x); acc[0] += w1 * f.x; acc[1] += w1 * f.y;
            f = __half22float2(*(__half2*)&gA1.y); acc[2] += w1 * f.x; acc[3] += w1 * f.y;
            f = __half22float2(*(__half2*)&gA1.z); acc[4] += w1 * f.x; acc[5] += w1 * f.y;
            f = __half22float2(*(__half2*)&gA1.w); acc[6] += w1 * f.x; acc[7] += w1 * f.y;
        }

        // ---- edge B ----
        if (hasB) {
            if (edB.x != cur) {
                if (cur >= 0) {
#pragma unroll
                    for (int k = 0; k < 8; ++k)
                        acc[k] += __shfl_down_sync(full, acc[k], 8);
#pragma unroll
                    for (int k = 0; k < 8; ++k)
                        acc[k] += __shfl_down_sync(full, acc[k], 16);
                    if (lane < 8) {
#pragma unroll
                        for (int k = 0; k < 8; ++k)
                            atomicAdd(&d_oacc[(size_t)cur * 64 + lane * 8 + k], acc[k]);
                    }
#pragma unroll
                    for (int k = 0; k < 8; ++k) acc[k] = 0.f;
                }
                cur = edB.x;
                if (lane < 8) {
                    asrcv = __ldg(d_asrc + cur * 8 + lane);
                    rs = 1.f / __ldg(d_asum + cur * 8 + lane);
                }
            }
            float wl = 0.f;
            if (lane < 8) {
                float s = asrcv + adB;
                s = s >= 0.f ? s : 0.2f * s;
                s = fminf(2.f, fmaxf(-2.f, s));
                wl = __expf(s) * rs;
            }
            float w0 = __shfl_sync(full, wl, hA);
            float w1 = __shfl_sync(full, wl, hA + 4);
            float2 f;
            f = __half22float2(*(__half2*)&gB0.x); acc[0] += w0 * f.x; acc[1] += w0 * f.y;
            f = __half22float2(*(__half2*)&gB0.y); acc[2] += w0 * f.x; acc[3] += w0 * f.y;
            f = __half22float2(*(__half2*)&gB0.z); acc[4] += w0 * f.x; acc[5] += w0 * f.y;
            f = __half22float2(*(__half2*)&gB0.w); acc[6] += w0 * f.x; acc[7] += w0 * f.y;
            f = __half22float2(*(__half2*)&gB1.x); acc[0] += w1 * f.x; acc[1] += w1 * f.y;
            f = __half22float2(*(__half2*)&gB1.y); acc[2] += w1 * f.x; acc[3] += w1 * f.y;
            f = __half22float2(*(__half2*)&gB1.z); acc[4] += w1 * f.x; acc[5] += w1 * f.y;
            f = __half22float2(*(__half2*)&gB1.w); acc[6] += w1 * f.x; acc[7] += w1 * f.y;
        }
    }
    if (cur >= 0) {
#pragma unroll
        for (int k = 0; k < 8; ++k)
            acc[k] += __shfl_down_sync(full, acc[k], 8);
#pragma unroll
        for (int k = 0; k < 8; ++k)
            acc[k] += __shfl_down_sync(full, acc[k], 16);
        if (lane < 8) {
#pragma unroll
            for (int k = 0; k < 8; ++k)
                atomicAdd(&d_oacc[(size_t)cur * 64 + lane * 8 + k], acc[k]);
        }
    }
}

// ---------------- K5: final leaky ----------------
__global__ void k_final(float* __restrict__ out, int total) {
    int i = blockIdx.x * blockDim.x + threadIdx.x;
    if (i < total) out[i] = leaky(d_oacc[i]);
}

// ---------------- launch ----------------
extern "C" void kernel_launch(void* const* d_in, const int* in_sizes, int n_in,
                              void* d_out, int out_size) {
    const float* x     = (const float*)d_in[0];
    const int*   edges = (const int*)  d_in[1];
    const float* W     = (const float*)d_in[2];
    const float* a     = (const float*)d_in[3];
    const float* M     = (const float*)d_in[4];
    float* out = (float*)d_out;

    int N = in_sizes[0] / Fd;
    int E = in_sizes[1] / 2;

    k_prep<<<256, 256>>>(W, a, M, x, N);                               // #1
    k_alpha<<<(N + 15) / 16, 256>>>(x, N);                             // #2
    k_att<<<((E + 7) / 8 * 32 + 255) / 256, 256>>>(edges, E);          // #3
    dim3 mg((N + 63) / 64, 4);
    k_mma<<<mg, 256>>>(N);                                             // #4
    int nwarps = (E + CHUNK - 1) / CHUNK;
    k_edge<<<(nwarps * 32 + 255) / 256, 256>>>(edges, E);              // #5
    k_final<<<(N * Fd + 255) / 256, 256>>>(out, N * Fd);               // #6
}